// round 3
// baseline (speedup 1.0000x reference)
#include <cuda_runtime.h>
#include <cstddef>

// ---------------------------------------------------------------------------
// Problem constants
//   B=4, N=1024, D=1024, H=16, P=64, DFF=4096 ; rows (B*N) = 4096
// ---------------------------------------------------------------------------
constexpr size_t SZ  = (size_t)4096 * 1024;   // one (B*N, D) activation (4M floats)
constexpr size_t SZH = (size_t)4096 * 4096;   // one (B*N, DFF) activation (16M floats)

// Single scratch arena (192 MB), stage-aware overlay:
//   [0,      24M) : proj (q1,k1,v1,q2,k2,v2)   -- dead after attn kernel
//   [24M,    32M) : attn out (2 streams)       -- dead after LN kernel
//   [0,      32M) : MLP hidden h (2 streams)   -- overlays proj+attn (both dead)
//   [32M,    40M) : s1 residual (2 streams)    -- live until final GEMM
//   [40M,    48M) : z2 (2 streams)             -- live until MLP1 done
__device__ float g_scratch[48 * 1024 * 1024];

constexpr size_t OFF_PROJ = 0;
constexpr size_t OFF_ATTN = 6 * SZ;
constexpr size_t OFF_H    = 0;
constexpr size_t OFF_S1   = 8 * SZ;
constexpr size_t OFF_Z2   = 10 * SZ;

// ---------------------------------------------------------------------------
// Batched FP32 SGEMM: 128x128 block tile, BK=16, 8x8 per thread, double-buffered
// MODE 0: C = A@B + bias
// MODE 1: C = relu(A@B + bias)
// MODE 2: C = A@B + bias + add   (add row stride addld; C row stride ldc)
// ---------------------------------------------------------------------------
struct GemmSet { const float* A; const float* B; const float* bias; const float* add; float* C; };
struct GemmArgs { GemmSet s[6]; };

template<int MODE>
__global__ void __launch_bounds__(256, 2)
sgemm_kernel(GemmArgs args, int K, int N, int ldc, int addld)
{
    GemmSet gs = args.s[blockIdx.z];
    const float* __restrict__ A = gs.A;
    const float* __restrict__ B = gs.B;

    __shared__ float As[2][16][132];   // [buf][k][row] (A transposed), padded
    __shared__ float Bs[2][16][128];   // [buf][k][col]

    const int tid = threadIdx.x;
    const int tx  = tid & 15;
    const int ty  = tid >> 4;
    const int rowBase = blockIdx.y << 7;
    const int colBase = blockIdx.x << 7;

    const int aRow = tid >> 2;
    const int aCol = (tid & 3) << 2;
    const int bRow = tid >> 5;
    const int bCol = (tid & 31) << 2;

    const float* Ap0 = A + (size_t)(rowBase + aRow) * K + aCol;
    const float* Ap1 = Ap0 + (size_t)64 * K;
    const float* Bp0 = B + (size_t)bRow * N + colBase + bCol;
    const float* Bp1 = Bp0 + (size_t)8 * N;

    float acc[8][8];
    #pragma unroll
    for (int i = 0; i < 8; i++)
        #pragma unroll
        for (int j = 0; j < 8; j++) acc[i][j] = 0.f;

    {
        float4 a0 = *(const float4*)Ap0;
        float4 a1 = *(const float4*)Ap1;
        float4 b0 = *(const float4*)Bp0;
        float4 b1 = *(const float4*)Bp1;
        As[0][aCol+0][aRow] = a0.x; As[0][aCol+1][aRow] = a0.y;
        As[0][aCol+2][aRow] = a0.z; As[0][aCol+3][aRow] = a0.w;
        As[0][aCol+0][64+aRow] = a1.x; As[0][aCol+1][64+aRow] = a1.y;
        As[0][aCol+2][64+aRow] = a1.z; As[0][aCol+3][64+aRow] = a1.w;
        *(float4*)&Bs[0][bRow][bCol]   = b0;
        *(float4*)&Bs[0][bRow+8][bCol] = b1;
    }
    __syncthreads();

    const int nk = K >> 4;
    float4 pa0, pa1, pb0, pb1;
    for (int kt = 0; kt < nk; kt++) {
        const int  buf  = kt & 1;
        const bool more = (kt + 1 < nk);
        if (more) {
            pa0 = *(const float4*)(Ap0 + (kt + 1) * 16);
            pa1 = *(const float4*)(Ap1 + (kt + 1) * 16);
            pb0 = *(const float4*)(Bp0 + (size_t)(kt + 1) * 16 * N);
            pb1 = *(const float4*)(Bp1 + (size_t)(kt + 1) * 16 * N);
        }
        #pragma unroll
        for (int kk = 0; kk < 16; kk++) {
            float ra[8], rb[8];
            *(float4*)&ra[0] = *(const float4*)&As[buf][kk][(ty << 2)];
            *(float4*)&ra[4] = *(const float4*)&As[buf][kk][(ty << 2) + 64];
            *(float4*)&rb[0] = *(const float4*)&Bs[buf][kk][(tx << 2)];
            *(float4*)&rb[4] = *(const float4*)&Bs[buf][kk][(tx << 2) + 64];
            #pragma unroll
            for (int i = 0; i < 8; i++)
                #pragma unroll
                for (int j = 0; j < 8; j++)
                    acc[i][j] = fmaf(ra[i], rb[j], acc[i][j]);
        }
        if (more) {
            const int nb = buf ^ 1;
            As[nb][aCol+0][aRow] = pa0.x; As[nb][aCol+1][aRow] = pa0.y;
            As[nb][aCol+2][aRow] = pa0.z; As[nb][aCol+3][aRow] = pa0.w;
            As[nb][aCol+0][64+aRow] = pa1.x; As[nb][aCol+1][64+aRow] = pa1.y;
            As[nb][aCol+2][64+aRow] = pa1.z; As[nb][aCol+3][64+aRow] = pa1.w;
            *(float4*)&Bs[nb][bRow][bCol]   = pb0;
            *(float4*)&Bs[nb][bRow+8][bCol] = pb1;
        }
        __syncthreads();
    }

    #pragma unroll
    for (int i = 0; i < 8; i++) {
        const int row = rowBase + ((i < 4) ? (ty << 2) + i : 60 + (ty << 2) + i);
        float* cp = gs.C + (size_t)row * ldc;
        const float* ap = (MODE == 2) ? (gs.add + (size_t)row * addld) : nullptr;
        #pragma unroll
        for (int q = 0; q < 2; q++) {
            const int col = colBase + (tx << 2) + q * 64;
            float4 v;
            v.x = acc[i][q*4+0] + gs.bias[col+0];
            v.y = acc[i][q*4+1] + gs.bias[col+1];
            v.z = acc[i][q*4+2] + gs.bias[col+2];
            v.w = acc[i][q*4+3] + gs.bias[col+3];
            if (MODE == 1) {
                v.x = fmaxf(v.x, 0.f); v.y = fmaxf(v.y, 0.f);
                v.z = fmaxf(v.z, 0.f); v.w = fmaxf(v.w, 0.f);
            }
            if (MODE == 2) {
                float4 a4 = *(const float4*)&ap[col];
                v.x += a4.x; v.y += a4.y; v.z += a4.z; v.w += a4.w;
            }
            *(float4*)&cp[col] = v;
        }
    }
}

// ---------------------------------------------------------------------------
// Fused cross-attention per (row-tile 128, head, batch, stream).
// Logits are tiny, so softmax = exp(s)/sum(exp(s)) without max subtraction.
// ---------------------------------------------------------------------------
constexpr int ATTN_PAD   = 68;
constexpr int ATTN_SMEMF = ATTN_PAD * (128 + 64 + 64 + 128);
constexpr int ATTN_SMEM  = ATTN_SMEMF * 4;   // 104448 bytes

__global__ void __launch_bounds__(256, 1)
attn_kernel(const float* __restrict__ proj, float* __restrict__ attnB)
{
    extern __shared__ float sm[];
    float* Qs = sm;                        // [128][68]
    float* Kt = sm + 128 * ATTN_PAD;       // [64][68] transposed (p, j)
    float* Vs = Kt + 64 * ATTN_PAD;        // [64][68]
    float* Ps = Vs + 64 * ATTN_PAD;        // [128][68]

    const int tid = threadIdx.x;
    const int tx  = tid & 15;
    const int ty  = tid >> 4;
    const int s   = blockIdx.z;
    const int bh  = blockIdx.y;
    const int b   = bh >> 4;
    const int h   = bh & 15;
    const int i0  = blockIdx.x << 7;
    const int hc  = h << 6;

    const float* Q  = proj + (size_t)(s ? 0 : 3) * SZ;
    const float* Kp = proj + (size_t)(s ? 4 : 1) * SZ;
    const float* Vp = proj + (size_t)(s ? 5 : 2) * SZ;
    float*       O  = attnB + (size_t)s * SZ;

    const size_t qbase = (size_t)(b * 1024 + i0) * 1024 + hc;

    #pragma unroll
    for (int t = 0; t < 8; t++) {
        int idx = tid + t * 256;
        int ir = idx >> 4;
        int pc = (idx & 15) << 2;
        *(float4*)&Qs[ir * ATTN_PAD + pc] =
            *(const float4*)&Q[qbase + (size_t)ir * 1024 + pc];
    }

    float oacc[8][4];
    float lpart[8];
    #pragma unroll
    for (int r = 0; r < 8; r++) {
        lpart[r] = 0.f;
        oacc[r][0] = oacc[r][1] = oacc[r][2] = oacc[r][3] = 0.f;
    }
    __syncthreads();

    for (int j0 = 0; j0 < 1024; j0 += 64) {
        const size_t kbase = (size_t)(b * 1024 + j0) * 1024 + hc;
        #pragma unroll
        for (int t = 0; t < 4; t++) {
            int idx = tid + t * 256;
            int jr = idx >> 4;
            int pc = (idx & 15) << 2;
            float4 kv = *(const float4*)&Kp[kbase + (size_t)jr * 1024 + pc];
            Kt[(pc + 0) * ATTN_PAD + jr] = kv.x;
            Kt[(pc + 1) * ATTN_PAD + jr] = kv.y;
            Kt[(pc + 2) * ATTN_PAD + jr] = kv.z;
            Kt[(pc + 3) * ATTN_PAD + jr] = kv.w;
            *(float4*)&Vs[jr * ATTN_PAD + pc] =
                *(const float4*)&Vp[kbase + (size_t)jr * 1024 + pc];
        }
        __syncthreads();

        float sacc[8][4];
        #pragma unroll
        for (int r = 0; r < 8; r++)
            sacc[r][0] = sacc[r][1] = sacc[r][2] = sacc[r][3] = 0.f;

        #pragma unroll 8
        for (int p = 0; p < 64; p++) {
            float4 kb = *(const float4*)&Kt[p * ATTN_PAD + (tx << 2)];
            #pragma unroll
            for (int r = 0; r < 8; r++) {
                float qa = Qs[(ty * 8 + r) * ATTN_PAD + p];
                sacc[r][0] = fmaf(qa, kb.x, sacc[r][0]);
                sacc[r][1] = fmaf(qa, kb.y, sacc[r][1]);
                sacc[r][2] = fmaf(qa, kb.z, sacc[r][2]);
                sacc[r][3] = fmaf(qa, kb.w, sacc[r][3]);
            }
        }

        #pragma unroll
        for (int r = 0; r < 8; r++) {
            float4 e;
            e.x = __expf(sacc[r][0] * 0.125f);
            e.y = __expf(sacc[r][1] * 0.125f);
            e.z = __expf(sacc[r][2] * 0.125f);
            e.w = __expf(sacc[r][3] * 0.125f);
            lpart[r] += (e.x + e.y) + (e.z + e.w);
            *(float4*)&Ps[(ty * 8 + r) * ATTN_PAD + (tx << 2)] = e;
        }
        __syncthreads();

        #pragma unroll 8
        for (int j = 0; j < 64; j++) {
            float4 vb = *(const float4*)&Vs[j * ATTN_PAD + (tx << 2)];
            #pragma unroll
            for (int r = 0; r < 8; r++) {
                float pe = Ps[(ty * 8 + r) * ATTN_PAD + j];
                oacc[r][0] = fmaf(pe, vb.x, oacc[r][0]);
                oacc[r][1] = fmaf(pe, vb.y, oacc[r][1]);
                oacc[r][2] = fmaf(pe, vb.z, oacc[r][2]);
                oacc[r][3] = fmaf(pe, vb.w, oacc[r][3]);
            }
        }
        __syncthreads();
    }

    float* lbuf = Kt;
    #pragma unroll
    for (int r = 0; r < 8; r++) lbuf[(ty * 8 + r) * 16 + tx] = lpart[r];
    __syncthreads();
    float* lsum = Vs;
    if (tid < 128) {
        float t = 0.f;
        #pragma unroll
        for (int q = 0; q < 16; q++) t += lbuf[tid * 16 + q];
        lsum[tid] = 1.0f / t;
    }
    __syncthreads();
    #pragma unroll
    for (int r = 0; r < 8; r++) {
        float inv = lsum[ty * 8 + r];
        float4 v = make_float4(oacc[r][0] * inv, oacc[r][1] * inv,
                               oacc[r][2] * inv, oacc[r][3] * inv);
        *(float4*)&O[qbase + (size_t)(ty * 8 + r) * 1024 + (tx << 2)] = v;
    }
}

// ---------------------------------------------------------------------------
// Fused: s1 = LN1(x) + attn ; z2 = LN2(s1)
// ---------------------------------------------------------------------------
struct LnArgs { const float* g1[2]; const float* b1[2]; const float* g2[2]; const float* b2[2]; };

__device__ __forceinline__ float blockReduceSum(float v, float* sbuf)
{
    #pragma unroll
    for (int o = 16; o; o >>= 1) v += __shfl_xor_sync(0xffffffffu, v, o);
    __syncthreads();
    if ((threadIdx.x & 31) == 0) sbuf[threadIdx.x >> 5] = v;
    __syncthreads();
    float t = sbuf[0];
    #pragma unroll
    for (int i = 1; i < 8; i++) t += sbuf[i];
    return t;
}

__global__ void __launch_bounds__(256)
ln_fused_kernel(const float* __restrict__ x1, const float* __restrict__ x2,
                LnArgs la, const float* __restrict__ attnB,
                float* __restrict__ s1B, float* __restrict__ z2B)
{
    __shared__ float sbuf[8];
    const int s   = blockIdx.y;
    const int row = blockIdx.x;
    const int c   = threadIdx.x << 2;
    const size_t off = (size_t)s * SZ + (size_t)row * 1024 + c;
    const float* X = (s ? x2 : x1);

    float4 xv = *(const float4*)&X[(size_t)row * 1024 + c];
    float4 av = *(const float4*)&attnB[off];

    float sum = (xv.x + xv.y) + (xv.z + xv.w);
    float ssq = xv.x*xv.x + xv.y*xv.y + xv.z*xv.z + xv.w*xv.w;
    sum = blockReduceSum(sum, sbuf);
    ssq = blockReduceSum(ssq, sbuf);
    const float inv = 1.0f / 1024.0f;
    float mu   = sum * inv;
    float var  = ssq * inv - mu * mu;
    float rstd = rsqrtf(var + 1e-5f);

    float4 g  = *(const float4*)&la.g1[s][c];
    float4 bb = *(const float4*)&la.b1[s][c];
    float4 sv;
    sv.x = (xv.x - mu) * rstd * g.x + bb.x + av.x;
    sv.y = (xv.y - mu) * rstd * g.y + bb.y + av.y;
    sv.z = (xv.z - mu) * rstd * g.z + bb.z + av.z;
    sv.w = (xv.w - mu) * rstd * g.w + bb.w + av.w;
    *(float4*)&s1B[off] = sv;

    float sum2 = (sv.x + sv.y) + (sv.z + sv.w);
    float ssq2 = sv.x*sv.x + sv.y*sv.y + sv.z*sv.z + sv.w*sv.w;
    sum2 = blockReduceSum(sum2, sbuf);
    ssq2 = blockReduceSum(ssq2, sbuf);
    float mu2   = sum2 * inv;
    float var2  = ssq2 * inv - mu2 * mu2;
    float rstd2 = rsqrtf(var2 + 1e-5f);

    float4 g2 = *(const float4*)&la.g2[s][c];
    float4 b2 = *(const float4*)&la.b2[s][c];
    float4 zv;
    zv.x = (sv.x - mu2) * rstd2 * g2.x + b2.x;
    zv.y = (sv.y - mu2) * rstd2 * g2.y + b2.y;
    zv.z = (sv.z - mu2) * rstd2 * g2.z + b2.z;
    zv.w = (sv.w - mu2) * rstd2 * g2.w + b2.w;
    *(float4*)&z2B[off] = zv;
}

// ---------------------------------------------------------------------------
// Host launcher
// Input order: x_1, x_2, (wq1,bq1,wk1,bk1,wv1,bv1,wq2,bq2,wk2,bk2,wv2,bv2),
//   h1: ln1_g,ln1_b,ln2_g,ln2_b,mlp_w1,mlp_b1,mlp_w2,mlp_b2, h2: same (14..29)
// ---------------------------------------------------------------------------
extern "C" void kernel_launch(void* const* d_in, const int* in_sizes, int n_in,
                              void* d_out, int out_size)
{
    (void)in_sizes; (void)n_in; (void)out_size;
    const float* x1 = (const float*)d_in[0];
    const float* x2 = (const float*)d_in[1];
    float* out = (float*)d_out;

    static float* scratch = nullptr;
    static bool inited = false;
    if (!inited) {
        cudaGetSymbolAddress((void**)&scratch, g_scratch);
        cudaFuncSetAttribute(attn_kernel, cudaFuncAttributeMaxDynamicSharedMemorySize, ATTN_SMEM);
        inited = true;
    }
    float* proj = scratch + OFF_PROJ;
    float* attn = scratch + OFF_ATTN;
    float* hb   = scratch + OFF_H;     // overlays proj+attn (dead by MLP1)
    float* s1b  = scratch + OFF_S1;
    float* z2b  = scratch + OFF_Z2;

    // 1) QKV projections
    GemmArgs qa{};
    for (int z = 0; z < 6; z++) {
        qa.s[z].A    = (z < 3) ? x1 : x2;
        qa.s[z].B    = (const float*)d_in[2 + 2 * z];
        qa.s[z].bias = (const float*)d_in[3 + 2 * z];
        qa.s[z].add  = nullptr;
        qa.s[z].C    = proj + (size_t)z * SZ;
    }
    sgemm_kernel<0><<<dim3(8, 32, 6), 256>>>(qa, 1024, 1024, 1024, 0);

    // 2) Cross attention
    attn_kernel<<<dim3(8, 64, 2), 256, ATTN_SMEM>>>(proj, attn);

    // 3) Fused LN1 + residual + LN2
    LnArgs la;
    for (int z = 0; z < 2; z++) {
        la.g1[z] = (const float*)d_in[14 + 8 * z];
        la.b1[z] = (const float*)d_in[15 + 8 * z];
        la.g2[z] = (const float*)d_in[16 + 8 * z];
        la.b2[z] = (const float*)d_in[17 + 8 * z];
    }
    ln_fused_kernel<<<dim3(4096, 2), 256>>>(x1, x2, la, attn, s1b, z2b);

    // 4) MLP layer 1: h = relu(z2 @ w1 + b1)   (h overlays proj/attn: both dead)
    GemmArgs m1{};
    for (int z = 0; z < 2; z++) {
        m1.s[z].A    = z2b + (size_t)z * SZ;
        m1.s[z].B    = (const float*)d_in[18 + 8 * z];
        m1.s[z].bias = (const float*)d_in[19 + 8 * z];
        m1.s[z].add  = nullptr;
        m1.s[z].C    = hb + (size_t)z * SZH;
    }
    sgemm_kernel<1><<<dim3(32, 32, 2), 256>>>(m1, 1024, 4096, 4096, 0);

    // 5) MLP layer 2 + residual -> concatenated output (ldc=2048)
    GemmArgs m2{};
    for (int z = 0; z < 2; z++) {
        m2.s[z].A    = hb + (size_t)z * SZH;
        m2.s[z].B    = (const float*)d_in[20 + 8 * z];
        m2.s[z].bias = (const float*)d_in[21 + 8 * z];
        m2.s[z].add  = s1b + (size_t)z * SZ;
        m2.s[z].C    = out + z * 1024;
    }
    sgemm_kernel<2><<<dim3(8, 32, 2), 256>>>(m2, 4096, 1024, 2048, 1024);
}

// round 4
// speedup vs baseline: 1.6802x; 1.6802x over previous
#include <cuda_runtime.h>
#include <cuda_bf16.h>
#include <cstddef>
#include <cstdint>

// ---------------------------------------------------------------------------
// Problem constants:  B=4, N=1024, D=1024, H=16, P=64, DFF=4096 ; rows = 4096
// ---------------------------------------------------------------------------
constexpr size_t SZ  = (size_t)4096 * 1024;
constexpr size_t SZH = (size_t)4096 * 4096;

// Scratch arena (192 MB) with stage overlay (proj+attn dead before h is written)
__device__ float g_scratch[48 * 1024 * 1024];
constexpr size_t OFF_PROJ = 0;
constexpr size_t OFF_ATTN = 6 * SZ;
constexpr size_t OFF_H    = 0;        // overlays proj+attn
constexpr size_t OFF_S1   = 8 * SZ;
constexpr size_t OFF_Z2   = 10 * SZ;

// ---------------------------------------------------------------------------
// Tensor-core GEMM via mma.sync bf16 with 3xBF16 fp32-split.
//   C = A@B (+bias [+relu | +add]),  A: MxK row-major fp32, B: KxN row-major fp32
// Block tile 128x128, BK=32, 8 warps (2x4), warp tile 64x32, m16n8k16.
// ---------------------------------------------------------------------------
struct GemmSet { const float* A; const float* B; const float* bias; const float* add; float* C; };
struct GemmArgs { GemmSet s[6]; };

// SMEM geometry (bf16 elems). Row paddings chosen conflict-free for ldmatrix.
constexpr int A_ROW = 40;            // 32 + 8 pad  (80B row: banks shift by 20)
constexpr int A_VER = 128 * A_ROW;   // one version (hi or lo)
constexpr int A_BUF = 2 * A_VER;
constexpr int B_ROW = 136;           // 128 + 8 pad (272B row: banks shift by 4)
constexpr int B_VER = 32 * B_ROW;
constexpr int B_BUF = 2 * B_VER;
constexpr int GEMM_SMEM = (2 * A_BUF + 2 * B_BUF) * 2;   // 75776 bytes

__device__ __forceinline__ uint32_t cvta_s(const void* p)
{ return (uint32_t)__cvta_generic_to_shared(p); }

__device__ __forceinline__ void ldsm_x4(uint32_t& r0, uint32_t& r1, uint32_t& r2, uint32_t& r3, uint32_t a)
{
    asm volatile("ldmatrix.sync.aligned.m8n8.x4.shared.b16 {%0,%1,%2,%3}, [%4];"
                 : "=r"(r0), "=r"(r1), "=r"(r2), "=r"(r3) : "r"(a));
}
__device__ __forceinline__ void ldsm_x4_t(uint32_t& r0, uint32_t& r1, uint32_t& r2, uint32_t& r3, uint32_t a)
{
    asm volatile("ldmatrix.sync.aligned.m8n8.x4.trans.shared.b16 {%0,%1,%2,%3}, [%4];"
                 : "=r"(r0), "=r"(r1), "=r"(r2), "=r"(r3) : "r"(a));
}
__device__ __forceinline__ void mma_bf16(float* c, const uint32_t* a, const uint32_t* b)
{
    asm volatile("mma.sync.aligned.m16n8k16.row.col.f32.bf16.bf16.f32 "
                 "{%0,%1,%2,%3}, {%4,%5,%6,%7}, {%8,%9}, {%0,%1,%2,%3};"
                 : "+f"(c[0]), "+f"(c[1]), "+f"(c[2]), "+f"(c[3])
                 : "r"(a[0]), "r"(a[1]), "r"(a[2]), "r"(a[3]), "r"(b[0]), "r"(b[1]));
}

__device__ __forceinline__ void split4(float4 v, __nv_bfloat16* hi, __nv_bfloat16* lo)
{
    __nv_bfloat16 h0 = __float2bfloat16_rn(v.x);
    __nv_bfloat16 h1 = __float2bfloat16_rn(v.y);
    __nv_bfloat16 h2 = __float2bfloat16_rn(v.z);
    __nv_bfloat16 h3 = __float2bfloat16_rn(v.w);
    ((__nv_bfloat162*)hi)[0] = __halves2bfloat162(h0, h1);
    ((__nv_bfloat162*)hi)[1] = __halves2bfloat162(h2, h3);
    float l0 = v.x - __bfloat162float(h0);
    float l1 = v.y - __bfloat162float(h1);
    float l2 = v.z - __bfloat162float(h2);
    float l3 = v.w - __bfloat162float(h3);
    ((__nv_bfloat162*)lo)[0] = __floats2bfloat162_rn(l0, l1);
    ((__nv_bfloat162*)lo)[1] = __floats2bfloat162_rn(l2, l3);
}

template<int MODE>
__global__ void __launch_bounds__(256, 1)
tgemm_kernel(GemmArgs args, int K, int N, int ldc, int addld)
{
    extern __shared__ __nv_bfloat16 smem[];
    __nv_bfloat16* As = smem;                 // [2 buf][2 ver][128][A_ROW]
    __nv_bfloat16* Bs = smem + 2 * A_BUF;     // [2 buf][2 ver][32][B_ROW]

    GemmSet gs = args.s[blockIdx.z];
    const float* __restrict__ A = gs.A;
    const float* __restrict__ B = gs.B;

    const int tid  = threadIdx.x;
    const int lane = tid & 31;
    const int wid  = tid >> 5;
    const int wm   = (wid & 1) << 6;    // warp m offset (0/64)
    const int wn   = (wid >> 1) << 5;   // warp n offset (0/32/64/96)
    const int rowBase = blockIdx.y << 7;
    const int colBase = blockIdx.x << 7;

    // ldmatrix per-thread address components
    const int a_r = (lane & 7) | (((lane >> 3) & 1) << 3);  // row within 16
    const int a_k = (lane >> 4) << 3;                        // 0 / 8
    const int b_k = a_r;                                     // same pattern
    const int b_n = a_k;

    const uint32_t As_s = cvta_s(As);
    const uint32_t Bs_s = cvta_s(Bs);

    // global load mapping (4 float4 each for A and B per thread)
    int ar[4], ac[4], br[4], bc[4];
    const float* Ap[4];
    const float* Bp[4];
    #pragma unroll
    for (int i = 0; i < 4; i++) {
        int idx = tid + i * 256;
        ar[i] = idx >> 3;  ac[i] = (idx & 7) << 2;
        br[i] = idx >> 5;  bc[i] = (idx & 31) << 2;
        Ap[i] = A + (size_t)(rowBase + ar[i]) * K + ac[i];
        Bp[i] = B + (size_t)br[i] * N + colBase + bc[i];
    }

    float acc[4][4][4];
    #pragma unroll
    for (int mt = 0; mt < 4; mt++)
        #pragma unroll
        for (int nt = 0; nt < 4; nt++)
            acc[mt][nt][0] = acc[mt][nt][1] = acc[mt][nt][2] = acc[mt][nt][3] = 0.f;

    // preload tile 0
    float4 av[4], bv[4];
    #pragma unroll
    for (int i = 0; i < 4; i++) { av[i] = *(const float4*)Ap[i]; bv[i] = *(const float4*)Bp[i]; }
    #pragma unroll
    for (int i = 0; i < 4; i++) {
        split4(av[i], &As[ar[i] * A_ROW + ac[i]], &As[A_VER + ar[i] * A_ROW + ac[i]]);
        split4(bv[i], &Bs[br[i] * B_ROW + bc[i]], &Bs[B_VER + br[i] * B_ROW + bc[i]]);
    }
    __syncthreads();

    const int nk = K >> 5;
    for (int kt = 0; kt < nk; kt++) {
        const int  buf  = kt & 1;
        const bool more = (kt + 1 < nk);
        if (more) {
            #pragma unroll
            for (int i = 0; i < 4; i++) {
                av[i] = *(const float4*)(Ap[i] + (kt + 1) * 32);
                bv[i] = *(const float4*)(Bp[i] + (size_t)(kt + 1) * 32 * N);
            }
        }

        // MMA over this buffer (BK=32 -> kk in {0,16})
        const uint32_t aBufOff = (uint32_t)(buf * A_BUF) * 2 + As_s;
        const uint32_t bBufOff = (uint32_t)(buf * B_BUF) * 2 + Bs_s;
        #pragma unroll
        for (int kk = 0; kk < 32; kk += 16) {
            uint32_t aH[4][4], aL[4][4], bH[4][2], bL[4][2];
            #pragma unroll
            for (int mt = 0; mt < 4; mt++) {
                uint32_t off = ((wm + mt * 16 + a_r) * A_ROW + kk + a_k) * 2;
                ldsm_x4(aH[mt][0], aH[mt][1], aH[mt][2], aH[mt][3], aBufOff + off);
                ldsm_x4(aL[mt][0], aL[mt][1], aL[mt][2], aL[mt][3], aBufOff + (uint32_t)A_VER * 2 + off);
            }
            #pragma unroll
            for (int p = 0; p < 2; p++) {
                uint32_t off = ((kk + b_k) * B_ROW + wn + p * 16 + b_n) * 2;
                ldsm_x4_t(bH[2*p][0], bH[2*p][1], bH[2*p+1][0], bH[2*p+1][1], bBufOff + off);
                ldsm_x4_t(bL[2*p][0], bL[2*p][1], bL[2*p+1][0], bL[2*p+1][1], bBufOff + (uint32_t)B_VER * 2 + off);
            }
            #pragma unroll
            for (int mt = 0; mt < 4; mt++)
                #pragma unroll
                for (int nt = 0; nt < 4; nt++) {
                    mma_bf16(acc[mt][nt], aH[mt], bH[nt]);
                    mma_bf16(acc[mt][nt], aH[mt], bL[nt]);
                    mma_bf16(acc[mt][nt], aL[mt], bH[nt]);
                }
        }

        if (more) {
            const int nb = buf ^ 1;
            #pragma unroll
            for (int i = 0; i < 4; i++) {
                split4(av[i], &As[nb * A_BUF + ar[i] * A_ROW + ac[i]],
                              &As[nb * A_BUF + A_VER + ar[i] * A_ROW + ac[i]]);
                split4(bv[i], &Bs[nb * B_BUF + br[i] * B_ROW + bc[i]],
                              &Bs[nb * B_BUF + B_VER + br[i] * B_ROW + bc[i]]);
            }
        }
        __syncthreads();
    }

    // Epilogue
    #pragma unroll
    for (int nt = 0; nt < 4; nt++) {
        const int col = colBase + wn + nt * 8 + ((lane & 3) << 1);
        const float2 bias2 = *(const float2*)&gs.bias[col];
        #pragma unroll
        for (int mt = 0; mt < 4; mt++) {
            const int row0 = rowBase + wm + mt * 16 + (lane >> 2);
            const int row1 = row0 + 8;
            float2 v0 = make_float2(acc[mt][nt][0] + bias2.x, acc[mt][nt][1] + bias2.y);
            float2 v1 = make_float2(acc[mt][nt][2] + bias2.x, acc[mt][nt][3] + bias2.y);
            if (MODE == 1) {
                v0.x = fmaxf(v0.x, 0.f); v0.y = fmaxf(v0.y, 0.f);
                v1.x = fmaxf(v1.x, 0.f); v1.y = fmaxf(v1.y, 0.f);
            }
            if (MODE == 2) {
                float2 a0 = *(const float2*)&gs.add[(size_t)row0 * addld + col];
                float2 a1 = *(const float2*)&gs.add[(size_t)row1 * addld + col];
                v0.x += a0.x; v0.y += a0.y; v1.x += a1.x; v1.y += a1.y;
            }
            *(float2*)&gs.C[(size_t)row0 * ldc + col] = v0;
            *(float2*)&gs.C[(size_t)row1 * ldc + col] = v1;
        }
    }
}

// ---------------------------------------------------------------------------
// Fused cross-attention (FP32; unchanged from passing R3 kernel)
// ---------------------------------------------------------------------------
constexpr int ATTN_PAD   = 68;
constexpr int ATTN_SMEMF = ATTN_PAD * (128 + 64 + 64 + 128);
constexpr int ATTN_SMEM  = ATTN_SMEMF * 4;

__global__ void __launch_bounds__(256, 1)
attn_kernel(const float* __restrict__ proj, float* __restrict__ attnB)
{
    extern __shared__ float sm[];
    float* Qs = sm;
    float* Kt = sm + 128 * ATTN_PAD;
    float* Vs = Kt + 64 * ATTN_PAD;
    float* Ps = Vs + 64 * ATTN_PAD;

    const int tid = threadIdx.x;
    const int tx  = tid & 15;
    const int ty  = tid >> 4;
    const int s   = blockIdx.z;
    const int bh  = blockIdx.y;
    const int b   = bh >> 4;
    const int h   = bh & 15;
    const int i0  = blockIdx.x << 7;
    const int hc  = h << 6;

    const float* Q  = proj + (size_t)(s ? 0 : 3) * SZ;
    const float* Kp = proj + (size_t)(s ? 4 : 1) * SZ;
    const float* Vp = proj + (size_t)(s ? 5 : 2) * SZ;
    float*       O  = attnB + (size_t)s * SZ;

    const size_t qbase = (size_t)(b * 1024 + i0) * 1024 + hc;

    #pragma unroll
    for (int t = 0; t < 8; t++) {
        int idx = tid + t * 256;
        int ir = idx >> 4;
        int pc = (idx & 15) << 2;
        *(float4*)&Qs[ir * ATTN_PAD + pc] =
            *(const float4*)&Q[qbase + (size_t)ir * 1024 + pc];
    }

    float oacc[8][4];
    float lpart[8];
    #pragma unroll
    for (int r = 0; r < 8; r++) {
        lpart[r] = 0.f;
        oacc[r][0] = oacc[r][1] = oacc[r][2] = oacc[r][3] = 0.f;
    }
    __syncthreads();

    for (int j0 = 0; j0 < 1024; j0 += 64) {
        const size_t kbase = (size_t)(b * 1024 + j0) * 1024 + hc;
        #pragma unroll
        for (int t = 0; t < 4; t++) {
            int idx = tid + t * 256;
            int jr = idx >> 4;
            int pc = (idx & 15) << 2;
            float4 kv = *(const float4*)&Kp[kbase + (size_t)jr * 1024 + pc];
            Kt[(pc + 0) * ATTN_PAD + jr] = kv.x;
            Kt[(pc + 1) * ATTN_PAD + jr] = kv.y;
            Kt[(pc + 2) * ATTN_PAD + jr] = kv.z;
            Kt[(pc + 3) * ATTN_PAD + jr] = kv.w;
            *(float4*)&Vs[jr * ATTN_PAD + pc] =
                *(const float4*)&Vp[kbase + (size_t)jr * 1024 + pc];
        }
        __syncthreads();

        float sacc[8][4];
        #pragma unroll
        for (int r = 0; r < 8; r++)
            sacc[r][0] = sacc[r][1] = sacc[r][2] = sacc[r][3] = 0.f;

        #pragma unroll 8
        for (int p = 0; p < 64; p++) {
            float4 kb = *(const float4*)&Kt[p * ATTN_PAD + (tx << 2)];
            #pragma unroll
            for (int r = 0; r < 8; r++) {
                float qa = Qs[(ty * 8 + r) * ATTN_PAD + p];
                sacc[r][0] = fmaf(qa, kb.x, sacc[r][0]);
                sacc[r][1] = fmaf(qa, kb.y, sacc[r][1]);
                sacc[r][2] = fmaf(qa, kb.z, sacc[r][2]);
                sacc[r][3] = fmaf(qa, kb.w, sacc[r][3]);
            }
        }

        #pragma unroll
        for (int r = 0; r < 8; r++) {
            float4 e;
            e.x = __expf(sacc[r][0] * 0.125f);
            e.y = __expf(sacc[r][1] * 0.125f);
            e.z = __expf(sacc[r][2] * 0.125f);
            e.w = __expf(sacc[r][3] * 0.125f);
            lpart[r] += (e.x + e.y) + (e.z + e.w);
            *(float4*)&Ps[(ty * 8 + r) * ATTN_PAD + (tx << 2)] = e;
        }
        __syncthreads();

        #pragma unroll 8
        for (int j = 0; j < 64; j++) {
            float4 vb = *(const float4*)&Vs[j * ATTN_PAD + (tx << 2)];
            #pragma unroll
            for (int r = 0; r < 8; r++) {
                float pe = Ps[(ty * 8 + r) * ATTN_PAD + j];
                oacc[r][0] = fmaf(pe, vb.x, oacc[r][0]);
                oacc[r][1] = fmaf(pe, vb.y, oacc[r][1]);
                oacc[r][2] = fmaf(pe, vb.z, oacc[r][2]);
                oacc[r][3] = fmaf(pe, vb.w, oacc[r][3]);
            }
        }
        __syncthreads();
    }

    float* lbuf = Kt;
    #pragma unroll
    for (int r = 0; r < 8; r++) lbuf[(ty * 8 + r) * 16 + tx] = lpart[r];
    __syncthreads();
    float* lsum = Vs;
    if (tid < 128) {
        float t = 0.f;
        #pragma unroll
        for (int q = 0; q < 16; q++) t += lbuf[tid * 16 + q];
        lsum[tid] = 1.0f / t;
    }
    __syncthreads();
    #pragma unroll
    for (int r = 0; r < 8; r++) {
        float inv = lsum[ty * 8 + r];
        float4 v = make_float4(oacc[r][0] * inv, oacc[r][1] * inv,
                               oacc[r][2] * inv, oacc[r][3] * inv);
        *(float4*)&O[qbase + (size_t)(ty * 8 + r) * 1024 + (tx << 2)] = v;
    }
}

// ---------------------------------------------------------------------------
// Fused: s1 = LN1(x) + attn ; z2 = LN2(s1)
// ---------------------------------------------------------------------------
struct LnArgs { const float* g1[2]; const float* b1[2]; const float* g2[2]; const float* b2[2]; };

__device__ __forceinline__ float blockReduceSum(float v, float* sbuf)
{
    #pragma unroll
    for (int o = 16; o; o >>= 1) v += __shfl_xor_sync(0xffffffffu, v, o);
    __syncthreads();
    if ((threadIdx.x & 31) == 0) sbuf[threadIdx.x >> 5] = v;
    __syncthreads();
    float t = sbuf[0];
    #pragma unroll
    for (int i = 1; i < 8; i++) t += sbuf[i];
    return t;
}

__global__ void __launch_bounds__(256)
ln_fused_kernel(const float* __restrict__ x1, const float* __restrict__ x2,
                LnArgs la, const float* __restrict__ attnB,
                float* __restrict__ s1B, float* __restrict__ z2B)
{
    __shared__ float sbuf[8];
    const int s   = blockIdx.y;
    const int row = blockIdx.x;
    const int c   = threadIdx.x << 2;
    const size_t off = (size_t)s * SZ + (size_t)row * 1024 + c;
    const float* X = (s ? x2 : x1);

    float4 xv = *(const float4*)&X[(size_t)row * 1024 + c];
    float4 av = *(const float4*)&attnB[off];

    float sum = (xv.x + xv.y) + (xv.z + xv.w);
    float ssq = xv.x*xv.x + xv.y*xv.y + xv.z*xv.z + xv.w*xv.w;
    sum = blockReduceSum(sum, sbuf);
    ssq = blockReduceSum(ssq, sbuf);
    const float inv = 1.0f / 1024.0f;
    float mu   = sum * inv;
    float var  = ssq * inv - mu * mu;
    float rstd = rsqrtf(var + 1e-5f);

    float4 g  = *(const float4*)&la.g1[s][c];
    float4 bb = *(const float4*)&la.b1[s][c];
    float4 sv;
    sv.x = (xv.x - mu) * rstd * g.x + bb.x + av.x;
    sv.y = (xv.y - mu) * rstd * g.y + bb.y + av.y;
    sv.z = (xv.z - mu) * rstd * g.z + bb.z + av.z;
    sv.w = (xv.w - mu) * rstd * g.w + bb.w + av.w;
    *(float4*)&s1B[off] = sv;

    float sum2 = (sv.x + sv.y) + (sv.z + sv.w);
    float ssq2 = sv.x*sv.x + sv.y*sv.y + sv.z*sv.z + sv.w*sv.w;
    sum2 = blockReduceSum(sum2, sbuf);
    ssq2 = blockReduceSum(ssq2, sbuf);
    float mu2   = sum2 * inv;
    float var2  = ssq2 * inv - mu2 * mu2;
    float rstd2 = rsqrtf(var2 + 1e-5f);

    float4 g2 = *(const float4*)&la.g2[s][c];
    float4 b2 = *(const float4*)&la.b2[s][c];
    float4 zv;
    zv.x = (sv.x - mu2) * rstd2 * g2.x + b2.x;
    zv.y = (sv.y - mu2) * rstd2 * g2.y + b2.y;
    zv.z = (sv.z - mu2) * rstd2 * g2.z + b2.z;
    zv.w = (sv.w - mu2) * rstd2 * g2.w + b2.w;
    *(float4*)&z2B[off] = zv;
}

// ---------------------------------------------------------------------------
// Host launcher
// ---------------------------------------------------------------------------
extern "C" void kernel_launch(void* const* d_in, const int* in_sizes, int n_in,
                              void* d_out, int out_size)
{
    (void)in_sizes; (void)n_in; (void)out_size;
    const float* x1 = (const float*)d_in[0];
    const float* x2 = (const float*)d_in[1];
    float* out = (float*)d_out;

    static float* scratch = nullptr;
    static bool inited = false;
    if (!inited) {
        cudaGetSymbolAddress((void**)&scratch, g_scratch);
        cudaFuncSetAttribute(attn_kernel,     cudaFuncAttributeMaxDynamicSharedMemorySize, ATTN_SMEM);
        cudaFuncSetAttribute(tgemm_kernel<0>, cudaFuncAttributeMaxDynamicSharedMemorySize, GEMM_SMEM);
        cudaFuncSetAttribute(tgemm_kernel<1>, cudaFuncAttributeMaxDynamicSharedMemorySize, GEMM_SMEM);
        cudaFuncSetAttribute(tgemm_kernel<2>, cudaFuncAttributeMaxDynamicSharedMemorySize, GEMM_SMEM);
        inited = true;
    }
    float* proj = scratch + OFF_PROJ;
    float* attn = scratch + OFF_ATTN;
    float* hb   = scratch + OFF_H;
    float* s1b  = scratch + OFF_S1;
    float* z2b  = scratch + OFF_Z2;

    // 1) QKV projections
    GemmArgs qa{};
    for (int z = 0; z < 6; z++) {
        qa.s[z].A    = (z < 3) ? x1 : x2;
        qa.s[z].B    = (const float*)d_in[2 + 2 * z];
        qa.s[z].bias = (const float*)d_in[3 + 2 * z];
        qa.s[z].add  = nullptr;
        qa.s[z].C    = proj + (size_t)z * SZ;
    }
    tgemm_kernel<0><<<dim3(8, 32, 6), 256, GEMM_SMEM>>>(qa, 1024, 1024, 1024, 0);

    // 2) Cross attention
    attn_kernel<<<dim3(8, 64, 2), 256, ATTN_SMEM>>>(proj, attn);

    // 3) Fused LN1 + residual + LN2
    LnArgs la;
    for (int z = 0; z < 2; z++) {
        la.g1[z] = (const float*)d_in[14 + 8 * z];
        la.b1[z] = (const float*)d_in[15 + 8 * z];
        la.g2[z] = (const float*)d_in[16 + 8 * z];
        la.b2[z] = (const float*)d_in[17 + 8 * z];
    }
    ln_fused_kernel<<<dim3(4096, 2), 256>>>(x1, x2, la, attn, s1b, z2b);

    // 4) MLP layer 1: h = relu(z2 @ w1 + b1)
    GemmArgs m1{};
    for (int z = 0; z < 2; z++) {
        m1.s[z].A    = z2b + (size_t)z * SZ;
        m1.s[z].B    = (const float*)d_in[18 + 8 * z];
        m1.s[z].bias = (const float*)d_in[19 + 8 * z];
        m1.s[z].add  = nullptr;
        m1.s[z].C    = hb + (size_t)z * SZH;
    }
    tgemm_kernel<1><<<dim3(32, 32, 2), 256, GEMM_SMEM>>>(m1, 1024, 4096, 4096, 0);

    // 5) MLP layer 2 + residual -> concatenated output (ldc=2048)
    GemmArgs m2{};
    for (int z = 0; z < 2; z++) {
        m2.s[z].A    = hb + (size_t)z * SZH;
        m2.s[z].B    = (const float*)d_in[20 + 8 * z];
        m2.s[z].bias = (const float*)d_in[21 + 8 * z];
        m2.s[z].add  = s1b + (size_t)z * SZ;
        m2.s[z].C    = out + z * 1024;
    }
    tgemm_kernel<2><<<dim3(8, 32, 2), 256, GEMM_SMEM>>>(m2, 4096, 1024, 2048, 1024);
}